// round 4
// baseline (speedup 1.0000x reference)
#include <cuda_runtime.h>

// Problem constants
#define N_CB   8
#define VOCAB  1024
#define VHALF  512
#define PAIRS  256          // vocab pairs per block
#define CDIM   16
#define BATCH  8
#define HW     1024         // 32*32
#define DCH    128          // N_CB*CDIM
#define BHW    8192         // BATCH*HW
#define NITEMS 65536        // BHW * N_CB

// Output layout (float32, concatenated flat in reference order)
#define OFF_Q      0
#define OFF_IDX    1048576
#define OFF_COMMIT 1114112
#define OFF_NCB    1114113
#define OFF_NCNT   1245185
#define OFF_NW     1253377

#define DECAY_F 0.99f
#define ALPHA_F 0.01f
#define EPS_F   1e-5f

// cross-block argmin scratch: (monotone score bits << 32) | global vocab idx
__device__ unsigned long long vq_scratch[NITEMS];
// per-codebook n = sum(new_count) (computed analytically in vq_init)
__device__ float n_dev[N_CB];
// last-arrival counters per (cb, chunk)
__device__ int vq_arrive[N_CB * 32];

// ---------- f32x2 packed helpers ----------
static __device__ __forceinline__ unsigned long long pack2(float lo, float hi) {
    unsigned long long r;
    asm("mov.b64 %0, {%1,%2};" : "=l"(r) : "f"(lo), "f"(hi));
    return r;
}
static __device__ __forceinline__ void unpack2(unsigned long long v, float& lo, float& hi) {
    asm("mov.b64 {%0,%1}, %2;" : "=f"(lo), "=f"(hi) : "l"(v));
}
static __device__ __forceinline__ unsigned long long fma2(unsigned long long a,
                                                          unsigned long long b,
                                                          unsigned long long c) {
    unsigned long long d;
    asm("fma.rn.f32x2 %0, %1, %2, %3;" : "=l"(d) : "l"(a), "l"(b), "l"(c));
    return d;
}
// monotone float -> u32 (order-preserving for all finite floats)
static __device__ __forceinline__ unsigned int fkey(float s) {
    unsigned int b = __float_as_uint(s);
    return (b & 0x80000000u) ? ~b : (b | 0x80000000u);
}

// ---------- kernel 1: init EMA outputs + scratch + counters + per-cb n ----------
// grid 512 x 256
__global__ void vq_init(const float* __restrict__ ema_count,
                        const float* __restrict__ ema_weight,
                        float* __restrict__ out) {
    const int tid = threadIdx.x;
    const int i = blockIdx.x * blockDim.x + tid;
    if (i == 0) out[OFF_COMMIT] = 0.0f;
    if (i < N_CB * 32) vq_arrive[i] = 0;
    if (i < N_CB * VOCAB) out[OFF_NCNT + i] = DECAY_F * ema_count[i];
    if (i < N_CB * VOCAB * CDIM) out[OFF_NW + i] = DECAY_F * ema_weight[i];
    if (i < NITEMS) vq_scratch[i] = 0xFFFFFFFFFFFFFFFFull;

    // block 0 additionally computes n[cb] = 0.99*sum(ema_count[cb]) + 0.01*BHW
    if (blockIdx.x == 0) {
        __shared__ float red[8][8];   // [cb][warp]
        const int lane = tid & 31;
        const int wrp  = tid >> 5;    // 0..7
        #pragma unroll
        for (int cb = 0; cb < N_CB; cb++) {
            float s = ema_count[cb * VOCAB + tid]
                    + ema_count[cb * VOCAB + tid + 256]
                    + ema_count[cb * VOCAB + tid + 512]
                    + ema_count[cb * VOCAB + tid + 768];
            #pragma unroll
            for (int st = 16; st > 0; st >>= 1)
                s += __shfl_xor_sync(0xFFFFFFFFu, s, st);
            if (lane == 0) red[cb][wrp] = s;
        }
        __syncthreads();
        if (tid < N_CB) {
            float s = 0.0f;
            #pragma unroll
            for (int w = 0; w < 8; w++) s += red[tid][w];
            n_dev[tid] = DECAY_F * s + ALPHA_F * (float)BHW;
        }
    }
}

// ---------- kernel 2: distance sweep + argmin + fused epilogue ----------
// grid: (32, 8, 2) -> x: chunk of 256 positions, y: codebook, z: vocab half
// block: 128 threads, 2 positions per thread
// smem per vocab pair p (18 u64, 144B, 16B aligned):
//   [0..15]  (c[2p][j], c[2p+1][j]) for j=0..15
//   [16]     (0.5||c_2p||^2, 0.5||c_2p+1||^2)
//   [17]     pad
__global__ __launch_bounds__(128, 4) void vq_main(const float* __restrict__ z,
                                                  const float* __restrict__ cbs,
                                                  float* out) {
    __shared__ __align__(16) unsigned long long sm2[PAIRS * 18];   // 36864 B
    float* smf = (float*)sm2;

    const int cb    = blockIdx.y;
    const int vbase = blockIdx.z * VHALF;
    const int tid   = threadIdx.x;

    // Load this block's half-codebook, interleaving vocab pairs
    {
        const float* src = cbs + ((size_t)cb * VOCAB + vbase) * CDIM;  // 8192 floats
        #pragma unroll
        for (int t = 0; t < 64; t++) {
            int i = tid + t * 128;            // coalesced read
            int v = i >> 4, j = i & 15;
            smf[(v >> 1) * 36 + 2 * j + (v & 1)] = src[i];
        }
    }
    __syncthreads();
    // h pairs
    #pragma unroll
    for (int t = 0; t < 4; t++) {
        int v = tid + t * 128;
        int p = v >> 1, o = v & 1;
        const float* r = smf + p * 36 + o;
        float s = 0.0f;
        #pragma unroll
        for (int j = 0; j < CDIM; j++) { float c = r[2 * j]; s += c * c; }
        smf[p * 36 + 32 + o] = 0.5f * s;
    }
    __syncthreads();

    // two positions per thread
    const int p0  = blockIdx.x * 256 + tid;
    const int p1  = p0 + 128;
    const int b   = p0 >> 10;
    const int hw0 = p0 & (HW - 1);
    const int hw1 = p1 & (HW - 1);

    const float* zb = z + (size_t)b * DCH * HW + (size_t)cb * CDIM * HW;

    unsigned long long zz0[CDIM], zz1[CDIM];
    #pragma unroll
    for (int j = 0; j < CDIM; j++) {
        float a = zb[j * HW + hw0];
        float c = zb[j * HW + hw1];
        zz0[j] = pack2(-a, -a);
        zz1[j] = pack2(-c, -c);
    }

    float best0 = 3.0e38f, best1 = 3.0e38f;
    int   bi0 = 0, bi1 = 0;

    #pragma unroll 2
    for (int p = 0; p < PAIRS; p++) {
        const ulonglong2* row = reinterpret_cast<const ulonglong2*>(sm2 + p * 18);
        const unsigned long long h = sm2[p * 18 + 16];
        ulonglong2 r0 = row[0], r1 = row[1], r2 = row[2], r3 = row[3];
        ulonglong2 r4 = row[4], r5 = row[5], r6 = row[6], r7 = row[7];

        unsigned long long a0, a1;
        a0 = fma2(zz0[0],  r0.x, h);  a1 = fma2(zz1[0],  r0.x, h);
        a0 = fma2(zz0[1],  r0.y, a0); a1 = fma2(zz1[1],  r0.y, a1);
        a0 = fma2(zz0[2],  r1.x, a0); a1 = fma2(zz1[2],  r1.x, a1);
        a0 = fma2(zz0[3],  r1.y, a0); a1 = fma2(zz1[3],  r1.y, a1);
        a0 = fma2(zz0[4],  r2.x, a0); a1 = fma2(zz1[4],  r2.x, a1);
        a0 = fma2(zz0[5],  r2.y, a0); a1 = fma2(zz1[5],  r2.y, a1);
        a0 = fma2(zz0[6],  r3.x, a0); a1 = fma2(zz1[6],  r3.x, a1);
        a0 = fma2(zz0[7],  r3.y, a0); a1 = fma2(zz1[7],  r3.y, a1);
        a0 = fma2(zz0[8],  r4.x, a0); a1 = fma2(zz1[8],  r4.x, a1);
        a0 = fma2(zz0[9],  r4.y, a0); a1 = fma2(zz1[9],  r4.y, a1);
        a0 = fma2(zz0[10], r5.x, a0); a1 = fma2(zz1[10], r5.x, a1);
        a0 = fma2(zz0[11], r5.y, a0); a1 = fma2(zz1[11], r5.y, a1);
        a0 = fma2(zz0[12], r6.x, a0); a1 = fma2(zz1[12], r6.x, a1);
        a0 = fma2(zz0[13], r6.y, a0); a1 = fma2(zz1[13], r6.y, a1);
        a0 = fma2(zz0[14], r7.x, a0); a1 = fma2(zz1[14], r7.x, a1);
        a0 = fma2(zz0[15], r7.y, a0); a1 = fma2(zz1[15], r7.y, a1);

        float sv0, sw0, sv1, sw1;
        unpack2(a0, sv0, sw0);
        unpack2(a1, sv1, sw1);
        const int ve = 2 * p, vo = 2 * p + 1;
        bool t;
        t = sv0 < best0; best0 = t ? sv0 : best0; bi0 = t ? ve : bi0;
        t = sw0 < best0; best0 = t ? sw0 : best0; bi0 = t ? vo : bi0;
        t = sv1 < best1; best1 = t ? sv1 : best1; bi1 = t ? ve : bi1;
        t = sw1 < best1; best1 = t ? sw1 : best1; bi1 = t ? vo : bi1;
    }

    // combine across vocab halves (ties -> smaller idx, matching argmin)
    unsigned long long* sc = vq_scratch + (size_t)cb * BHW;
    atomicMin(&sc[p0], ((unsigned long long)fkey(best0) << 32) | (unsigned)(vbase + bi0));
    atomicMin(&sc[p1], ((unsigned long long)fkey(best1) << 32) | (unsigned)(vbase + bi1));

    // ---- last-arrival fused epilogue ----
    __threadfence();                      // release our atomicMin results
    __syncthreads();
    __shared__ int arrive_old;
    if (tid == 0)
        arrive_old = atomicAdd(&vq_arrive[cb * 32 + blockIdx.x], 1);
    __syncthreads();
    if (arrive_old != 1) return;          // first block leaves; second finishes
    __threadfence();                      // acquire the other block's results

    float* qout    = out + OFF_Q + (size_t)b * DCH * HW + (size_t)cb * CDIM * HW;
    float* nweight = out + OFF_NW;
    float locc = 0.0f;

    // position 0
    {
        const int bi = (int)(unsigned)sc[p0];
        const float* crow = cbs + ((size_t)cb * VOCAB + bi) * CDIM;
        float* wdst = nweight + ((size_t)cb * VOCAB + bi) * CDIM;
        #pragma unroll
        for (int j = 0; j < CDIM; j++) {
            float nzj, dup;
            unpack2(zz0[j], nzj, dup);
            const float zj = -nzj;
            const float cj = crow[j];
            qout[(size_t)j * HW + hw0] = zj + (cj - zj);   // match zq_st rounding
            const float d = zj - cj;
            locc += d * d;
            atomicAdd(&wdst[j], ALPHA_F * zj);
        }
        out[OFF_IDX + (size_t)b * (N_CB * HW) + (size_t)cb * HW + hw0] = (float)bi;
        atomicAdd(out + OFF_NCNT + cb * VOCAB + bi, ALPHA_F);
    }
    // position 1
    {
        const int bi = (int)(unsigned)sc[p1];
        const float* crow = cbs + ((size_t)cb * VOCAB + bi) * CDIM;
        float* wdst = nweight + ((size_t)cb * VOCAB + bi) * CDIM;
        #pragma unroll
        for (int j = 0; j < CDIM; j++) {
            float nzj, dup;
            unpack2(zz1[j], nzj, dup);
            const float zj = -nzj;
            const float cj = crow[j];
            qout[(size_t)j * HW + hw1] = zj + (cj - zj);
            const float d = zj - cj;
            locc += d * d;
            atomicAdd(&wdst[j], ALPHA_F * zj);
        }
        out[OFF_IDX + (size_t)b * (N_CB * HW) + (size_t)cb * HW + hw1] = (float)bi;
        atomicAdd(out + OFF_NCNT + cb * VOCAB + bi, ALPHA_F);
    }

    // commitment: shuffle reduce -> 1 atomic per finishing block
    #pragma unroll
    for (int st = 16; st > 0; st >>= 1)
        locc += __shfl_xor_sync(0xFFFFFFFFu, locc, st);
    __shared__ float red[4];
    if ((tid & 31) == 0) red[tid >> 5] = locc;
    __syncthreads();
    if (tid == 0)
        atomicAdd(out + OFF_COMMIT,
                  (red[0] + red[1] + red[2] + red[3]) * (1.0f / (float)(BHW * N_CB * CDIM)));
}

// ---------- kernel 3: normalized codebook update (wide grid) ----------
// grid 512 x 256, one output element per thread
__global__ __launch_bounds__(256) void vq_final(float* out) {
    const int i  = blockIdx.x * 256 + threadIdx.x;    // 0 .. 131071
    const int cb = i >> 14;
    const int v  = (i >> 4) & (VOCAB - 1);

    const float cnt = out[OFF_NCNT + cb * VOCAB + v];
    const float n   = n_dev[cb];
    const float countv = (cnt + EPS_F) / (n + VOCAB * EPS_F) * n;
    out[OFF_NCB + i] = __fdividef(out[OFF_NW + i], countv);
}

extern "C" void kernel_launch(void* const* d_in, const int* in_sizes, int n_in,
                              void* d_out, int out_size) {
    const float* z   = (const float*)d_in[0];
    const float* cbs = (const float*)d_in[1];
    const float* ec  = (const float*)d_in[2];
    const float* ew  = (const float*)d_in[3];
    float* out = (float*)d_out;

    vq_init<<<512, 256>>>(ec, ew, out);
    dim3 gmain(32, N_CB, 2);
    vq_main<<<gmain, 128>>>(z, cbs, out);
    vq_final<<<512, 256>>>(out);
}